// round 12
// baseline (speedup 1.0000x reference)
#include <cuda_runtime.h>
#include <cuda_bf16.h>
#include <math.h>

#define N_PROP   65536
#define N_GT     64
#define NCLS     81
#define TOTAL    512
#define MAX_POS  128

#define K1_TPB   1024
#define K1_NBLK  128            // 2 threads/prop, 512 props/block
#define PPB      512
#define K2_TPB   1024           // single block, 64 props/thread
#define K3_TPB   128
#define K3_NBLK  128            // 4 warps each -> 512 slots

// -------- device scratch --------
__device__ unsigned char g_resb[N_PROP];   // f | (gt<<2)
__device__ int   g_ent[TOTAL];             // idx:16 | gt:6 | pos at bit 31
__device__ float g_ce[TOTAL];
__device__ float g_rg[TOTAL];
__device__ int   g_done;

__device__ __forceinline__ float sl1(float d) {
    float ad = fabsf(d);
    return (ad < 1.0f) ? (0.5f * d * d) : (ad - 0.5f);
}

// ================= K1: IoU + classify (proven R11 phase-1) =================
__global__ void __launch_bounds__(K1_TPB, 1)
k_iou(const float* __restrict__ props, const float* __restrict__ gts) {
    __shared__ float4 sg[N_GT];
    __shared__ float  sS[N_GT];       // ga + 1e-8 (comparison fold)
    __shared__ float  sga[N_GT];      // raw ga (exact final union)
    __shared__ float  s_ci[PPB], s_cu[PPB];
    __shared__ int    s_cj[PPB];

    const int t   = threadIdx.x;
    const int bid = blockIdx.x;
    const int half = t >> 9;                 // 0: gts [0,32), 1: gts [32,64)
    const int lp   = t & (PPB - 1);

    if (t < N_GT) {
        float4 g = ((const float4*)gts)[t];
        float ga = (g.z - g.x) * (g.w - g.y);
        sg[t]  = g;
        sga[t] = ga;
        sS[t]  = ga + 1e-8f;
    }
    __syncthreads();

    const int i = bid * PPB + lp;
    const float4 p = ((const float4*)props)[i];
    const float pa = (p.z - p.x) * (p.w - p.y);

    const int j0 = half * 32;
    float biA, bSA, biB, bSB;
    int   bjA, bjB;
    {
        float4 g = sg[j0];
        float ix = fmaxf(fminf(p.z, g.z) - fmaxf(p.x, g.x), 0.f);
        float iy = fmaxf(fminf(p.w, g.w) - fmaxf(p.y, g.y), 0.f);
        biA = ix * iy; bSA = pa + sS[j0]; bjA = j0;
        g = sg[j0 + 16];
        ix = fmaxf(fminf(p.z, g.z) - fmaxf(p.x, g.x), 0.f);
        iy = fmaxf(fminf(p.w, g.w) - fmaxf(p.y, g.y), 0.f);
        biB = ix * iy; bSB = pa + sS[j0 + 16]; bjB = j0 + 16;
    }
#pragma unroll
    for (int j = 1; j < 16; j++) {
        int jA = j0 + j, jB = j0 + 16 + j;
        float4 gA = sg[jA], gB = sg[jB];
        float SA = pa + sS[jA], SB = pa + sS[jB];
        float ixA = fmaxf(fminf(p.z, gA.z) - fmaxf(p.x, gA.x), 0.f);
        float iyA = fmaxf(fminf(p.w, gA.w) - fmaxf(p.y, gA.y), 0.f);
        float ixB = fmaxf(fminf(p.z, gB.z) - fmaxf(p.x, gB.x), 0.f);
        float iyB = fmaxf(fminf(p.w, gB.w) - fmaxf(p.y, gB.y), 0.f);
        float inA = ixA * iyA, inB = ixB * iyB;
        // iou_new > iou_best <=> in*bS > bi*S (union -inter terms cancel exactly)
        if (inA * bSA > biA * SA) { biA = inA; bSA = SA; bjA = jA; }
        if (inB * bSB > biB * SB) { biB = inB; bSB = SB; bjB = jB; }
    }
    if (biB * bSA > biA * bSB) { biA = biB; bSA = bSB; bjA = bjB; }

    if (half == 1) { s_ci[lp] = biA; s_cu[lp] = bSA; s_cj[lp] = bjA; }
    __syncthreads();

    if (half == 0) {
        float ui = s_ci[lp], uS = s_cu[lp];
        if (ui * bSA > biA * uS) { biA = ui; bSA = uS; bjA = s_cj[lp]; }
        // exact final iou in reference association order
        float u = ((pa + sga[bjA]) - biA) + 1e-8f;
        float miou = biA / u;
        int f = (miou >= 0.5f) ? 1 : ((miou >= 0.1f) ? 2 : 0);
        g_resb[i] = (unsigned char)(f | (bjA << 2));
    }
}

// ================= K2: single-block scan + select =================
__global__ void __launch_bounds__(K2_TPB)
k_sel() {
    __shared__ int wsp[32], wsn[32];

    const int t = threadIdx.x;
    const int warp = t >> 5, lane = t & 31;
    const unsigned full = 0xffffffffu;

    // each thread owns 64 proposals = 16 ints of flags
    int rw[16];
    const int4* src = (const int4*)g_resb;
#pragma unroll
    for (int k = 0; k < 4; k++) {
        int4 v = src[t * 4 + k];
        rw[k * 4 + 0] = v.x; rw[k * 4 + 1] = v.y;
        rw[k * 4 + 2] = v.z; rw[k * 4 + 3] = v.w;
    }

    // count pos/neg among my 64
    int cp = 0, cn = 0;
#pragma unroll
    for (int k = 0; k < 16; k++) {
#pragma unroll
        for (int b = 0; b < 4; b++) {
            int f = (rw[k] >> (8 * b)) & 3;
            cp += (f == 1);
            cn += (f == 2);
        }
    }

    // block-wide inclusive scan of (cp, cn)
    int ip = cp, in_ = cn;
#pragma unroll
    for (int o = 1; o < 32; o <<= 1) {
        int a = __shfl_up_sync(full, ip, o);
        int b = __shfl_up_sync(full, in_, o);
        if (lane >= o) { ip += a; in_ += b; }
    }
    if (lane == 31) { wsp[warp] = ip; wsn[warp] = in_; }
    __syncthreads();
    if (warp == 0) {
        int vp = wsp[lane], vn = wsn[lane];
#pragma unroll
        for (int o = 1; o < 32; o <<= 1) {
            int a = __shfl_up_sync(full, vp, o);
            int b = __shfl_up_sync(full, vn, o);
            if (lane >= o) { vp += a; vn += b; }
        }
        wsp[lane] = vp; wsn[lane] = vn;
    }
    __syncthreads();
    const int basep = (warp > 0) ? wsp[warp - 1] : 0;
    const int basen = (warp > 0) ? wsn[warp - 1] : 0;
    const int posb = basep + ip - cp;          // exclusive pos rank base
    const int negb = basen + in_ - cn;         // exclusive neg rank base
    const int pos_total = wsp[31];
    const int neg_total = wsn[31];
    const int npos = min(pos_total, MAX_POS);

    // walk my 64 proposals in order, emit slot entries
    int rp = posb, rn = negb, ro = t * 64 - negb;   // non-neg rank base
#pragma unroll
    for (int k = 0; k < 16; k++) {
#pragma unroll
        for (int b = 0; b < 4; b++) {
            int v = (rw[k] >> (8 * b)) & 0xFF;
            int f = v & 3;
            int i = t * 64 + k * 4 + b;
            if (f == 1) {
                if (rp < npos)
                    g_ent[rp] = i | ((v >> 2) << 16) | (int)0x80000000;
                rp++;
            } else if (f == 2) {
                int s = npos + rn;
                if (rn < neg_total && s < TOTAL) g_ent[s] = i;
                rn++;
            }
            if (f != 2) {
                int s = npos + neg_total + ro;
                if (s < TOTAL) g_ent[s] = i;
                ro++;
            }
        }
    }
}

// ================= K3: loss + last-arriver reduce =================
__global__ void __launch_bounds__(K3_TPB)
k_loss(const float* __restrict__ props,
       const float* __restrict__ gts,
       const int*   __restrict__ gt_labels,
       const float* __restrict__ score,
       const float* __restrict__ txty,
       float* __restrict__ out) {
    __shared__ float4 sg[N_GT];
    __shared__ int    slbl[N_GT];
    __shared__ int    s_last;
    __shared__ float  rc[4], rr[4];

    const int t = threadIdx.x, bid = blockIdx.x;
    const int warp = t >> 5, lane = t & 31;
    const unsigned full = 0xffffffffu;

    if (t < N_GT) {
        sg[t] = ((const float4*)gts)[t];
        slbl[t] = gt_labels[t];
    }
    __syncthreads();

    {
        int slot = bid * 4 + warp;          // 128 blocks x 4 warps = 512 slots
        unsigned e = (unsigned)__ldcg(&g_ent[slot]);
        int  idx    = e & 0xFFFF;
        int  g      = (e >> 16) & 0x3F;
        bool is_pos = (e >> 31) != 0;
        int  lbl    = is_pos ? slbl[g] : 0;

        const float* row = score + (size_t)idx * NCLS;
        float v0 = row[lane];
        float v1 = row[lane + 32];
        float v2 = (lane + 64 < NCLS) ? row[lane + 64] : -INFINITY;
        float m = fmaxf(fmaxf(v0, v1), v2);
#pragma unroll
        for (int o = 16; o; o >>= 1) m = fmaxf(m, __shfl_xor_sync(full, m, o));
        float s = expf(v0 - m) + expf(v1 - m) + ((lane + 64 < NCLS) ? expf(v2 - m) : 0.0f);
#pragma unroll
        for (int o = 16; o; o >>= 1) s += __shfl_xor_sync(full, s, o);

        float cand = (lbl < 32) ? v0 : ((lbl < 64) ? v1 : v2);
        float vl = __shfl_sync(full, cand, lbl & 31);

        if (lane == 0) {
            float ce = m + logf(s) - vl;
            float rg = 0.0f;
            if (is_pos) {
                float4 pp = ((const float4*)props)[idx];
                float4 gb = sg[g];
                float pw = pp.z - pp.x, ph = pp.w - pp.y;
                float pcx = pp.x + 0.5f * pw, pcy = pp.y + 0.5f * ph;
                float gw = gb.z - gb.x, gh = gb.w - gb.y;
                float gcx = gb.x + 0.5f * gw, gcy = gb.y + 0.5f * gh;
                float t0 = ((gcx - pcx) / pw) * 10.0f;
                float t1 = ((gcy - pcy) / ph) * 10.0f;
                float t2 = logf(gw / pw) * 5.0f;
                float t3 = logf(gh / ph) * 5.0f;
                float4 pv = *(const float4*)(txty + ((size_t)idx * NCLS + g) * 4);
                rg = sl1(pv.x - t0) + sl1(pv.y - t1) + sl1(pv.z - t2) + sl1(pv.w - t3);
            }
            g_ce[slot] = ce;
            g_rg[slot] = rg;
        }
    }

    // last-arriving block reduces and resets replay state
    __syncthreads();
    if (t == 0) {
        __threadfence();
        s_last = (atomicAdd(&g_done, 1) == K3_NBLK - 1) ? 1 : 0;
    }
    __syncthreads();
    if (s_last) {
        __threadfence();
        float c  = __ldcg(&g_ce[t])       + __ldcg(&g_ce[t + 128])
                 + __ldcg(&g_ce[t + 256]) + __ldcg(&g_ce[t + 384]);
        float r2 = __ldcg(&g_rg[t])       + __ldcg(&g_rg[t + 128])
                 + __ldcg(&g_rg[t + 256]) + __ldcg(&g_rg[t + 384]);
#pragma unroll
        for (int o = 16; o; o >>= 1) {
            c  += __shfl_xor_sync(full, c, o);
            r2 += __shfl_xor_sync(full, r2, o);
        }
        if (lane == 0) { rc[warp] = c; rr[warp] = r2; }
        __syncthreads();
        if (warp == 0 && lane == 0) {
            float cc  = rc[0] + rc[1] + rc[2] + rc[3];
            float rrv = rr[0] + rr[1] + rr[2] + rr[3];
            out[0] = cc  * (1.0f / (float)TOTAL);
            out[1] = rrv * (1.0f / (float)TOTAL);
            g_done = 0;     // reset for next graph replay
        }
    }
}

extern "C" void kernel_launch(void* const* d_in, const int* in_sizes, int n_in,
                              void* d_out, int out_size) {
    const float* props = (const float*)d_in[1];
    const float* score = (const float*)d_in[2];
    const float* txty  = (const float*)d_in[3];
    const float* gts   = (const float*)d_in[4];
    const int*   glbl  = (const int*)d_in[5];
    float* out = (float*)d_out;

    k_iou <<<K1_NBLK, K1_TPB>>>(props, gts);
    k_sel <<<1,       K2_TPB>>>();
    k_loss<<<K3_NBLK, K3_TPB>>>(props, gts, glbl, score, txty, out);
}

// round 13
// speedup vs baseline: 1.3861x; 1.3861x over previous
#include <cuda_runtime.h>
#include <cuda_bf16.h>
#include <math.h>

#define N_PROP   65536
#define N_GT     64
#define NCLS     81
#define TOTAL    512
#define MAX_POS  128

#define K1_TPB   1024
#define K1_NBLK  128            // 2 threads/prop, 512 props/block
#define PPB      512
#define K2_TPB   1024
#define K2_NBLK  128            // 4 slots per block -> 512 slots

// -------- device scratch --------
__device__ unsigned char g_resb[N_PROP];   // f | (gt<<2)
__device__ float g_ce[TOTAL];
__device__ float g_rg[TOTAL];
__device__ int   g_done;

__device__ __forceinline__ float sl1(float d) {
    float ad = fabsf(d);
    return (ad < 1.0f) ? (0.5f * d * d) : (ad - 0.5f);
}

// ================= K1: IoU + classify (proven 7.6us config) =================
__global__ void __launch_bounds__(K1_TPB, 1)
k_iou(const float* __restrict__ props, const float* __restrict__ gts) {
    __shared__ float4 sg[N_GT];
    __shared__ float  sS[N_GT];       // ga + 1e-8 (comparison fold)
    __shared__ float  sga[N_GT];      // raw ga (exact final union)
    __shared__ float  s_ci[PPB], s_cu[PPB];
    __shared__ int    s_cj[PPB];

    const int t   = threadIdx.x;
    const int bid = blockIdx.x;
    const int half = t >> 9;                 // 0: gts [0,32), 1: gts [32,64)
    const int lp   = t & (PPB - 1);

    if (t < N_GT) {
        float4 g = ((const float4*)gts)[t];
        float ga = (g.z - g.x) * (g.w - g.y);
        sg[t]  = g;
        sga[t] = ga;
        sS[t]  = ga + 1e-8f;
    }
    __syncthreads();

    const int i = bid * PPB + lp;
    const float4 p = ((const float4*)props)[i];
    const float pa = (p.z - p.x) * (p.w - p.y);

    const int j0 = half * 32;
    float biA, bSA, biB, bSB;
    int   bjA, bjB;
    {
        float4 g = sg[j0];
        float ix = fmaxf(fminf(p.z, g.z) - fmaxf(p.x, g.x), 0.f);
        float iy = fmaxf(fminf(p.w, g.w) - fmaxf(p.y, g.y), 0.f);
        biA = ix * iy; bSA = pa + sS[j0]; bjA = j0;
        g = sg[j0 + 16];
        ix = fmaxf(fminf(p.z, g.z) - fmaxf(p.x, g.x), 0.f);
        iy = fmaxf(fminf(p.w, g.w) - fmaxf(p.y, g.y), 0.f);
        biB = ix * iy; bSB = pa + sS[j0 + 16]; bjB = j0 + 16;
    }
#pragma unroll
    for (int j = 1; j < 16; j++) {
        int jA = j0 + j, jB = j0 + 16 + j;
        float4 gA = sg[jA], gB = sg[jB];
        float SA = pa + sS[jA], SB = pa + sS[jB];
        float ixA = fmaxf(fminf(p.z, gA.z) - fmaxf(p.x, gA.x), 0.f);
        float iyA = fmaxf(fminf(p.w, gA.w) - fmaxf(p.y, gA.y), 0.f);
        float ixB = fmaxf(fminf(p.z, gB.z) - fmaxf(p.x, gB.x), 0.f);
        float iyB = fmaxf(fminf(p.w, gB.w) - fmaxf(p.y, gB.y), 0.f);
        float inA = ixA * iyA, inB = ixB * iyB;
        // iou_new > iou_best <=> in*bS > bi*S (union -inter terms cancel exactly)
        if (inA * bSA > biA * SA) { biA = inA; bSA = SA; bjA = jA; }
        if (inB * bSB > biB * SB) { biB = inB; bSB = SB; bjB = jB; }
    }
    if (biB * bSA > biA * bSB) { biA = biB; bSA = bSB; bjA = bjB; }

    if (half == 1) { s_ci[lp] = biA; s_cu[lp] = bSA; s_cj[lp] = bjA; }
    __syncthreads();

    if (half == 0) {
        float ui = s_ci[lp], uS = s_cu[lp];
        if (ui * bSA > biA * uS) { biA = ui; bSA = uS; bjA = s_cj[lp]; }
        // exact final iou in reference association order
        float u = ((pa + sga[bjA]) - biA) + 1e-8f;
        float miou = biA / u;
        int f = (miou >= 0.5f) ? 1 : ((miou >= 0.1f) ? 2 : 0);
        g_resb[i] = (unsigned char)(f | (bjA << 2));
    }
}

// find the need-th (0-based) matching byte among this thread's 64 flags
// mode 0: f==1 (returns idx | gt<<16 | 0x80000000), 1: f==2, 2: f!=2
__device__ __forceinline__ int find_kth(const int* rw, int t, int need, int mode) {
    for (int k = 0; k < 16; k++) {
        int w = rw[k];
        for (int b = 0; b < 4; b++) {
            int v = (w >> (8 * b)) & 0xFF;
            int f = v & 3;
            bool hit = (mode == 0) ? (f == 1) : (mode == 1) ? (f == 2) : (f != 2);
            if (hit) {
                if (need == 0) {
                    int i = t * 64 + k * 4 + b;
                    return (mode == 0) ? (i | ((v >> 2) << 16) | (int)0x80000000) : i;
                }
                need--;
            }
        }
    }
    return 0; // unreachable
}

// ================= K2: replicated select + loss + reduce (no barriers) ======
__global__ void __launch_bounds__(K2_TPB)
k_loss(const float* __restrict__ props,
       const float* __restrict__ gts,
       const int*   __restrict__ gt_labels,
       const float* __restrict__ score,
       const float* __restrict__ txty,
       float* __restrict__ out) {
    __shared__ int    wsp[32], wsn[32];
    __shared__ int    s_ent[4];
    __shared__ float4 sg[N_GT];
    __shared__ int    slbl[N_GT];
    __shared__ int    s_last;
    __shared__ float  rc[16], rr[16];

    const int t = threadIdx.x, bid = blockIdx.x;
    const int warp = t >> 5, lane = t & 31;
    const unsigned full = 0xffffffffu;

    if (t < N_GT) {
        sg[t] = ((const float4*)gts)[t];
        slbl[t] = gt_labels[t];
    }

    // ---- load my 64 flags (16 ints), count pos/neg via popc masks ----
    int rw[16];
    {
        const int4* src = (const int4*)g_resb;
#pragma unroll
        for (int k = 0; k < 4; k++) {
            int4 v = src[t * 4 + k];
            rw[k * 4 + 0] = v.x; rw[k * 4 + 1] = v.y;
            rw[k * 4 + 2] = v.z; rw[k * 4 + 3] = v.w;
        }
    }
    int cp = 0, cn = 0;
#pragma unroll
    for (int k = 0; k < 16; k++) {
        cp += __popc(rw[k] & 0x01010101);   // f==1 -> bit0 set (gt<<2 clears 0-1)
        cn += __popc(rw[k] & 0x02020202);   // f==2 -> bit1 set
    }

    // ---- block-wide scan over 1024 threads ----
    int ip = cp, in_ = cn;
#pragma unroll
    for (int o = 1; o < 32; o <<= 1) {
        int a = __shfl_up_sync(full, ip, o);
        int b = __shfl_up_sync(full, in_, o);
        if (lane >= o) { ip += a; in_ += b; }
    }
    if (lane == 31) { wsp[warp] = ip; wsn[warp] = in_; }
    __syncthreads();
    if (warp == 0) {
        int vp = wsp[lane], vn = wsn[lane];
#pragma unroll
        for (int o = 1; o < 32; o <<= 1) {
            int a = __shfl_up_sync(full, vp, o);
            int b = __shfl_up_sync(full, vn, o);
            if (lane >= o) { vp += a; vn += b; }
        }
        wsp[lane] = vp; wsn[lane] = vn;
    }
    __syncthreads();
    const int basep = (warp > 0) ? wsp[warp - 1] : 0;
    const int basen = (warp > 0) ? wsn[warp - 1] : 0;
    const int posb = basep + ip - cp;          // my exclusive pos rank base
    const int negb = basen + in_ - cn;         // my exclusive neg rank base
    const int pos_total = wsp[31];
    const int neg_total = wsn[31];
    const int npos = min(pos_total, MAX_POS);

    // ---- targeted walk: materialize only this block's 4 slots ----
#pragma unroll
    for (int sl = 0; sl < 4; sl++) {
        int s = bid * 4 + sl;
        if (s < npos) {
            if (s >= posb && s < posb + cp)
                s_ent[sl] = find_kth(rw, t, s - posb, 0);
        } else if (s < npos + neg_total) {
            int r = s - npos;
            if (r >= negb && r < negb + cn)
                s_ent[sl] = find_kth(rw, t, r - negb, 1);
        } else {
            int r = s - npos - neg_total;
            int rob = t * 64 - negb;           // my non-neg rank base
            int cno = 64 - cn;
            if (r >= rob && r < rob + cno)
                s_ent[sl] = find_kth(rw, t, r - rob, 2);
        }
    }
    __syncthreads();

    // ---- loss: warps 0-3 own the 4 slots ----
    if (warp < 4) {
        int slot = bid * 4 + warp;
        unsigned e = (unsigned)s_ent[warp];
        int  idx    = e & 0xFFFF;
        int  g      = (e >> 16) & 0x3F;
        bool is_pos = (e >> 31) != 0;
        int  lbl    = is_pos ? slbl[g] : 0;

        const float* row = score + (size_t)idx * NCLS;
        float v0 = row[lane];
        float v1 = row[lane + 32];
        float v2 = (lane + 64 < NCLS) ? row[lane + 64] : -INFINITY;
        float m = fmaxf(fmaxf(v0, v1), v2);
#pragma unroll
        for (int o = 16; o; o >>= 1) m = fmaxf(m, __shfl_xor_sync(full, m, o));
        float s = expf(v0 - m) + expf(v1 - m) + ((lane + 64 < NCLS) ? expf(v2 - m) : 0.0f);
#pragma unroll
        for (int o = 16; o; o >>= 1) s += __shfl_xor_sync(full, s, o);

        float cand = (lbl < 32) ? v0 : ((lbl < 64) ? v1 : v2);
        float vl = __shfl_sync(full, cand, lbl & 31);

        if (lane == 0) {
            float ce = m + logf(s) - vl;
            float rg = 0.0f;
            if (is_pos) {
                float4 pp = ((const float4*)props)[idx];
                float4 gb = sg[g];
                float pw = pp.z - pp.x, ph = pp.w - pp.y;
                float pcx = pp.x + 0.5f * pw, pcy = pp.y + 0.5f * ph;
                float gw = gb.z - gb.x, gh = gb.w - gb.y;
                float gcx = gb.x + 0.5f * gw, gcy = gb.y + 0.5f * gh;
                float t0 = ((gcx - pcx) / pw) * 10.0f;
                float t1 = ((gcy - pcy) / ph) * 10.0f;
                float t2 = logf(gw / pw) * 5.0f;
                float t3 = logf(gh / ph) * 5.0f;
                float4 pv = *(const float4*)(txty + ((size_t)idx * NCLS + g) * 4);
                rg = sl1(pv.x - t0) + sl1(pv.y - t1) + sl1(pv.z - t2) + sl1(pv.w - t3);
            }
            g_ce[slot] = ce;
            g_rg[slot] = rg;
        }
    }

    // ---- last-arriving block reduces and resets ticket ----
    __syncthreads();
    if (t == 0) {
        __threadfence();
        s_last = (atomicAdd(&g_done, 1) == K2_NBLK - 1) ? 1 : 0;
    }
    __syncthreads();
    if (s_last) {
        if (t < TOTAL) {
            __threadfence();
            float c  = __ldcg(&g_ce[t]);
            float r2 = __ldcg(&g_rg[t]);
#pragma unroll
            for (int o = 16; o; o >>= 1) {
                c  += __shfl_xor_sync(full, c, o);
                r2 += __shfl_xor_sync(full, r2, o);
            }
            if (lane == 0) { rc[warp] = c; rr[warp] = r2; }
        }
        __syncthreads();
        if (warp == 0) {
            float cc  = (lane < 16) ? rc[lane] : 0.0f;
            float rrv = (lane < 16) ? rr[lane] : 0.0f;
#pragma unroll
            for (int o = 8; o; o >>= 1) {
                cc  += __shfl_xor_sync(full, cc, o);
                rrv += __shfl_xor_sync(full, rrv, o);
            }
            if (lane == 0) {
                out[0] = cc  * (1.0f / (float)TOTAL);
                out[1] = rrv * (1.0f / (float)TOTAL);
                g_done = 0;     // reset for next graph replay
            }
        }
    }
}

extern "C" void kernel_launch(void* const* d_in, const int* in_sizes, int n_in,
                              void* d_out, int out_size) {
    const float* props = (const float*)d_in[1];
    const float* score = (const float*)d_in[2];
    const float* txty  = (const float*)d_in[3];
    const float* gts   = (const float*)d_in[4];
    const int*   glbl  = (const int*)d_in[5];
    float* out = (float*)d_out;

    k_iou <<<K1_NBLK, K1_TPB>>>(props, gts);
    k_loss<<<K2_NBLK, K2_TPB>>>(props, gts, glbl, score, txty, out);
}

// round 14
// speedup vs baseline: 1.9806x; 1.4289x over previous
#include <cuda_runtime.h>
#include <cuda_bf16.h>
#include <math.h>

#define N_PROP   65536
#define N_GT     64
#define NCLS     81
#define TOTAL    512
#define MAX_POS  128
#define TPB      1024
#define NBLK     128
#define PPB      512
#define NCHUNK   256            // chunks of 256 proposals

// -------- device scratch --------
__device__ unsigned char g_resb[N_PROP];   // f | (gt<<2)
__device__ int   g_ckp[NCHUNK];
__device__ int   g_ckn[NCHUNK];
__device__ float g_ce[TOTAL];
__device__ float g_rg[TOTAL];
__device__ int          g_cntA[32];
__device__ volatile int g_genA[32];
__device__ int          g_done;

__device__ __forceinline__ float sl1(float d) {
    float ad = fabsf(d);
    return (ad < 1.0f) ? (0.5f * d * d) : (ad - 0.5f);
}

__global__ void __launch_bounds__(TPB, 1)
k_fused(const float* __restrict__ props,
        const float* __restrict__ gts,
        const int*   __restrict__ gt_labels,
        const float* __restrict__ score,
        const float* __restrict__ txty,
        float* __restrict__ out) {
    __shared__ float4 sg[N_GT];
    __shared__ float  sS[N_GT];
    __shared__ float  sga[N_GT];
    __shared__ int    slbl[N_GT];
    __shared__ float  s_ci[PPB], s_cu[PPB];
    __shared__ int    s_cj[PPB];
    __shared__ int    wpc[16], wnc[16];
    __shared__ int    swp[8], swn[8];
    __shared__ int    ssp[NCHUNK], ssn[NCHUNK];   // inclusive scans
    __shared__ int    s_numpos, s_negtot;
    __shared__ int    s_last;
    __shared__ float  rc[16], rr[16];

    const int t    = threadIdx.x;
    const int bid  = blockIdx.x;
    const int warp = t >> 5, lane = t & 31;
    const int half = t >> 9;
    const int lp   = t & (PPB - 1);
    const unsigned full = 0xffffffffu;

    // ---- stage gt data ----
    if (t < N_GT) {
        float4 g = ((const float4*)gts)[t];
        float ga = (g.z - g.x) * (g.w - g.y);
        sg[t]  = g;
        sga[t] = ga;
        sS[t]  = ga + 1e-8f;
        slbl[t] = gt_labels[t];
    }
    __syncthreads();

    // ============ phase 1: IoU argmax (proven) ============
    const int i = bid * PPB + lp;
    const float4 p = ((const float4*)props)[i];
    const float pa = (p.z - p.x) * (p.w - p.y);

    const int j0 = half * 32;
    float biA, bSA, biB, bSB;
    int   bjA, bjB;
    {
        float4 g = sg[j0];
        float ix = fmaxf(fminf(p.z, g.z) - fmaxf(p.x, g.x), 0.f);
        float iy = fmaxf(fminf(p.w, g.w) - fmaxf(p.y, g.y), 0.f);
        biA = ix * iy; bSA = pa + sS[j0]; bjA = j0;
        g = sg[j0 + 16];
        ix = fmaxf(fminf(p.z, g.z) - fmaxf(p.x, g.x), 0.f);
        iy = fmaxf(fminf(p.w, g.w) - fmaxf(p.y, g.y), 0.f);
        biB = ix * iy; bSB = pa + sS[j0 + 16]; bjB = j0 + 16;
    }
#pragma unroll
    for (int j = 1; j < 16; j++) {
        int jA = j0 + j, jB = j0 + 16 + j;
        float4 gA = sg[jA], gB = sg[jB];
        float SA = pa + sS[jA], SB = pa + sS[jB];
        float ixA = fmaxf(fminf(p.z, gA.z) - fmaxf(p.x, gA.x), 0.f);
        float iyA = fmaxf(fminf(p.w, gA.w) - fmaxf(p.y, gA.y), 0.f);
        float ixB = fmaxf(fminf(p.z, gB.z) - fmaxf(p.x, gB.x), 0.f);
        float iyB = fmaxf(fminf(p.w, gB.w) - fmaxf(p.y, gB.y), 0.f);
        float inA = ixA * iyA, inB = ixB * iyB;
        // iou_new > iou_best <=> in*bS > bi*S (union -inter terms cancel exactly)
        if (inA * bSA > biA * SA) { biA = inA; bSA = SA; bjA = jA; }
        if (inB * bSB > biB * SB) { biB = inB; bSB = SB; bjB = jB; }
    }
    if (biB * bSA > biA * bSB) { biA = biB; bSA = bSB; bjA = bjB; }

    if (half == 1) { s_ci[lp] = biA; s_cu[lp] = bSA; s_cj[lp] = bjA; }
    __syncthreads();

    int f = 0;
    unsigned bp = 0, bn = 0;
    if (half == 0) {
        float ui = s_ci[lp], uS = s_cu[lp];
        if (ui * bSA > biA * uS) { biA = ui; bSA = uS; bjA = s_cj[lp]; }
        float u = ((pa + sga[bjA]) - biA) + 1e-8f;   // exact reference assoc order
        float miou = biA / u;
        f = (miou >= 0.5f) ? 1 : ((miou >= 0.1f) ? 2 : 0);
        g_resb[i] = (unsigned char)(f | (bjA << 2));
        bp = __ballot_sync(full, f == 1);
        bn = __ballot_sync(full, f == 2);
        if (lane == 0) { wpc[warp] = __popc(bp); wnc[warp] = __popc(bn); }
    }
    __syncthreads();
    if (t < 2) {        // chunk counts: warps 0-7 -> chunk 2bid, 8-15 -> 2bid+1
        int cp = 0, cn = 0;
#pragma unroll
        for (int w = 0; w < 8; w++) { cp += wpc[t * 8 + w]; cn += wnc[t * 8 + w]; }
        g_ckp[2 * bid + t] = cp;
        g_ckn[2 * bid + t] = cn;
    }

    // ============ barrier A (the ONLY spin barrier) ============
    __syncthreads();
    if (t == 0) {
        __threadfence();
        if (atomicAdd(&g_cntA[0], 1) == NBLK - 1) {
            __threadfence();
            g_genA[0] = 1;
        } else {
            while (g_genA[0] == 0) { }
            __threadfence();
        }
    }
    __syncthreads();

    // ============ scan 256 chunk counts (warps 0-7) ============
    if (t < NCHUNK) {
        int ip  = __ldcg(&g_ckp[t]);
        int in_ = __ldcg(&g_ckn[t]);
#pragma unroll
        for (int o = 1; o < 32; o <<= 1) {
            int a = __shfl_up_sync(full, ip, o);
            int b = __shfl_up_sync(full, in_, o);
            if (lane >= o) { ip += a; in_ += b; }
        }
        if (lane == 31) { swp[warp] = ip; swn[warp] = in_; }
        __syncthreads();
        int basep = 0, basen = 0;
        for (int w = 0; w < warp; w++) { basep += swp[w]; basen += swn[w]; }
        ssp[t] = basep + ip;
        ssn[t] = basen + in_;
    } else {
        __syncthreads();
    }
    __syncthreads();
    if (t == 0) {
        s_numpos = min(ssp[NCHUNK - 1], MAX_POS);
        s_negtot = ssn[NCHUNK - 1];
    }
    __syncthreads();

    // ============ resolve + loss: warps 0-3 own slots 4bid+w ============
    if (warp < 4) {
        const int slot = bid * 4 + warp;
        const int npos = s_numpos, negt = s_negtot;
        int mode, r;
        bool is_pos = slot < npos;
        if (is_pos)                { mode = 0; r = slot; }
        else if (slot < npos + negt) { mode = 1; r = slot - npos; }
        else                       { mode = 2; r = slot - npos - negt; }

        // find owning chunk: unique c with cb(c) <= r < cb(c+1)  (lane-parallel)
        int found = 0;
#pragma unroll
        for (int k = 0; k < 8; k++) {
            int c = lane + 32 * k;
            int sp0 = (c > 0) ? ssp[c - 1] : 0;
            int sn0 = (c > 0) ? ssn[c - 1] : 0;
            int cb, ce_;
            if (mode == 0)      { cb = sp0;           ce_ = ssp[c]; }
            else if (mode == 1) { cb = sn0;           ce_ = ssn[c]; }
            else                { cb = c * 256 - sn0; ce_ = (c + 1) * 256 - ssn[c]; }
            if (cb <= r && r < ce_) found = c + 1;    // +1 so 0 = not found
        }
#pragma unroll
        for (int o = 16; o; o >>= 1) found = max(found, __shfl_xor_sync(full, found, o));
        const int c = found - 1;
        int cb;
        {
            int sp0 = (c > 0) ? ssp[c - 1] : 0;
            int sn0 = (c > 0) ? ssn[c - 1] : 0;
            cb = (mode == 0) ? sp0 : (mode == 1) ? sn0 : (c * 256 - sn0);
        }
        const int need_rank = r - cb;               // rank within chunk

        // load chunk flags: 256 bytes = 64 ints; lane l takes words 2l, 2l+1
        const int* cw = (const int*)g_resb + c * 64;
        int w0 = __ldcg(&cw[2 * lane]);
        int w1 = __ldcg(&cw[2 * lane + 1]);
        int myc;
        if (mode == 0)      myc = __popc(w0 & 0x01010101) + __popc(w1 & 0x01010101);
        else if (mode == 1) myc = __popc(w0 & 0x02020202) + __popc(w1 & 0x02020202);
        else                myc = 8 - __popc(w0 & 0x02020202) - __popc(w1 & 0x02020202);
        // exclusive scan of myc across warp
        int ex = myc;
#pragma unroll
        for (int o = 1; o < 32; o <<= 1) {
            int a = __shfl_up_sync(full, ex, o);
            if (lane >= o) ex += a;
        }
        ex -= myc;
        // the lane whose span contains need_rank walks its 8 bytes
        int ent = 0;
        if (need_rank >= ex && need_rank < ex + myc) {
            int need = need_rank - ex;
#pragma unroll
            for (int w2 = 0; w2 < 2; w2++) {
                int word = (w2 == 0) ? w0 : w1;
#pragma unroll
                for (int b = 0; b < 4; b++) {
                    int v = (word >> (8 * b)) & 0xFF;
                    int ff = v & 3;
                    bool hit = (mode == 0) ? (ff == 1) : (mode == 1) ? (ff == 2) : (ff != 2);
                    if (hit) {
                        if (need == 0) {
                            int idx = c * 256 + lane * 8 + w2 * 4 + b;
                            ent = idx | ((v >> 2) << 16);
                        }
                        need--;
                    }
                }
            }
        }
        // broadcast entry from owning lane
#pragma unroll
        for (int o = 16; o; o >>= 1) ent |= __shfl_xor_sync(full, ent, o);

        const int idx = ent & 0xFFFF;
        const int g   = (ent >> 16) & 0x3F;
        const int lbl = is_pos ? slbl[g] : 0;

        const float* row = score + (size_t)idx * NCLS;
        float v0 = row[lane];
        float v1 = row[lane + 32];
        float v2 = (lane + 64 < NCLS) ? row[lane + 64] : -INFINITY;
        float m = fmaxf(fmaxf(v0, v1), v2);
#pragma unroll
        for (int o = 16; o; o >>= 1) m = fmaxf(m, __shfl_xor_sync(full, m, o));
        float s = expf(v0 - m) + expf(v1 - m) + ((lane + 64 < NCLS) ? expf(v2 - m) : 0.0f);
#pragma unroll
        for (int o = 16; o; o >>= 1) s += __shfl_xor_sync(full, s, o);

        float cand = (lbl < 32) ? v0 : ((lbl < 64) ? v1 : v2);
        float vl = __shfl_sync(full, cand, lbl & 31);

        if (lane == 0) {
            float ce = m + logf(s) - vl;
            float rg = 0.0f;
            if (is_pos) {
                float4 pp = ((const float4*)props)[idx];
                float4 gb = sg[g];
                float pw = pp.z - pp.x, ph = pp.w - pp.y;
                float pcx = pp.x + 0.5f * pw, pcy = pp.y + 0.5f * ph;
                float gw = gb.z - gb.x, gh = gb.w - gb.y;
                float gcx = gb.x + 0.5f * gw, gcy = gb.y + 0.5f * gh;
                float t0 = ((gcx - pcx) / pw) * 10.0f;
                float t1 = ((gcy - pcy) / ph) * 10.0f;
                float t2 = logf(gw / pw) * 5.0f;
                float t3 = logf(gh / ph) * 5.0f;
                float4 pv = *(const float4*)(txty + ((size_t)idx * NCLS + g) * 4);
                rg = sl1(pv.x - t0) + sl1(pv.y - t1) + sl1(pv.z - t2) + sl1(pv.w - t3);
            }
            g_ce[slot] = ce;
            g_rg[slot] = rg;
        }
    }

    // ============ ticket + reduce (proven) ============
    __syncthreads();
    if (t == 0) {
        __threadfence();
        s_last = (atomicAdd(&g_done, 1) == NBLK - 1) ? 1 : 0;
    }
    __syncthreads();
    if (s_last) {
        if (t < TOTAL) {
            __threadfence();
            float c  = __ldcg(&g_ce[t]);
            float r2 = __ldcg(&g_rg[t]);
#pragma unroll
            for (int o = 16; o; o >>= 1) {
                c  += __shfl_xor_sync(full, c, o);
                r2 += __shfl_xor_sync(full, r2, o);
            }
            if (lane == 0) { rc[warp] = c; rr[warp] = r2; }
        }
        __syncthreads();
        if (warp == 0) {
            float cc  = (lane < 16) ? rc[lane] : 0.0f;
            float rrv = (lane < 16) ? rr[lane] : 0.0f;
#pragma unroll
            for (int o = 8; o; o >>= 1) {
                cc  += __shfl_xor_sync(full, cc, o);
                rrv += __shfl_xor_sync(full, rrv, o);
            }
            if (lane == 0) {
                out[0] = cc  * (1.0f / (float)TOTAL);
                out[1] = rrv * (1.0f / (float)TOTAL);
            }
        }
        if (t == 0) {
            g_cntA[0] = 0; g_genA[0] = 0; g_done = 0;   // reset for replay
        }
    }
}

extern "C" void kernel_launch(void* const* d_in, const int* in_sizes, int n_in,
                              void* d_out, int out_size) {
    const float* props = (const float*)d_in[1];
    const float* score = (const float*)d_in[2];
    const float* txty  = (const float*)d_in[3];
    const float* gts   = (const float*)d_in[4];
    const int*   glbl  = (const int*)d_in[5];
    float* out = (float*)d_out;

    k_fused<<<NBLK, TPB>>>(props, gts, glbl, score, txty, out);
}